// round 8
// baseline (speedup 1.0000x reference)
#include <cuda_runtime.h>

#define IMG    224
#define PSIDE  112
#define NPATCH 12544          // PSIDE*PSIDE
#define CHUNKS 49             // NPATCH / 256
#define NFEAT  (4 * NPATCH)
#define NC     10
#define NB     32
#define NBPB   4              // batches per block (W reuse factor)
#define NTHR   320            // 10 warps: stage1 uses 8, stage2 one warp/class

// per-block partial class sums: [batch][chunk][class]
__device__ float g_part[NB * CHUNKS * NC];

// ---------------------------------------------------------------------------
// Closed-form quantum block (exact reduction of: encode_ry ; RY(p0)w0 ;
// RX(p1)w1 ; CNOT(0,1) ; RZ(p2)w2 ; RY(p3)w3 ; CNOT(2,3) ; RX(p4)w2 ;
// RZ(p5)w0 ; measure Z), verified in the Heisenberg picture:
//   z0 = cos(d0 + p0)                                   (CNOT control only)
//   z1 = cos(d0 + p0) * cos(p1) * cos(d1)               (Z⊗Z product form)
//   z2 = cos(p4)*cos(d2) + sin(p4)*sin(p2)*sin(d2)*sin(d3 + p3)
//   z3 = cos(d3 + p3) * cos(d2)
// (RZ(p5) is diagonal -> cannot change Z-basis probabilities -> dropped.)
//
// g layout (5 floats per layer): [0]=p0  [1]=cos(p1)  [2]=cos(p4)
//                                [3]=sin(p4)*sin(p2)  [4]=p3
// ---------------------------------------------------------------------------
__device__ __forceinline__ void qblock(const float d[4], const float* g, float out[4]) {
    float s2, c2, sB, cB;
    __sincosf(d[2],        &s2, &c2);
    __sincosf(d[3] + g[4], &sB, &cB);
    const float z0 = __cosf(d[0] + g[0]);
    out[0] = z0;
    out[1] = z0 * g[1] * __cosf(d[1]);
    out[2] = g[2] * c2 + g[3] * s2 * sB;
    out[3] = cB * c2;
}

// ---------------- main kernel: patch extract + quantum blocks + block GEMM ----

__global__ __launch_bounds__(NTHR)
void quanv_kernel(const float* __restrict__ x,
                  const float* __restrict__ p1,
                  const float* __restrict__ p2,
                  const float* __restrict__ W) {
    __shared__ float  gc[10];              // 5 reduced constants per layer
    __shared__ float4 res_sm[NBPB][256];   // per-patch features, 16 KB

    const int tid = threadIdx.x;
    if (tid >= 256 && tid < 256 + 10) {    // spare warps compute gate constants
        const int k = tid - 256;
        const int layer = k / 5, s = k % 5;
        const float* pp = (layer == 0) ? p1 : p2;
        float v;
        if      (s == 0) v = pp[0];
        else if (s == 1) v = cosf(pp[1]);
        else if (s == 2) v = cosf(pp[4]);
        else if (s == 3) v = sinf(pp[4]) * sinf(pp[2]);
        else             v = pp[3];
        gc[layer * 5 + s] = v;
    }
    __syncthreads();

    const int chunk = blockIdx.y;

    // ---- stage 1: features for NBPB batches -> smem (first 8 warps) ---------
    if (tid < 256) {
        const int p  = chunk * 256 + tid;  // 0..12543
        const int pr = p / PSIDE, pc = p % PSIDE;
        const int r = 2 * pr, c = 2 * pc;
        const bool edge = (pc == PSIDE - 1);

#pragma unroll
        for (int b = 0; b < NBPB; ++b) {
            const int batch = blockIdx.x * NBPB + b;
            const float* xb = x + (size_t)batch * IMG * IMG + r * IMG + c;

            float d[4];
            float2 f01 = *(const float2*)xb;   // 8B aligned: c even
            d[0] = f01.x; d[1] = f01.y;
            if (edge) {                    // f2=x[r+1][c], f3=x[r+1][c+1]
                float2 f23 = *(const float2*)(xb + IMG);
                d[2] = f23.x; d[3] = f23.y;
            } else {                       // f2=x[r][c+2], f3=x[r+1][c]
                d[2] = xb[2];
                d[3] = xb[IMG];
            }

            float m[4], res[4];
            qblock(d, gc,     m);
            qblock(m, gc + 5, res);
            res_sm[b][tid] = make_float4(res[0] + m[0], res[1] + m[1],
                                         res[2] + m[2], res[3] + m[3]);
        }
    }
    __syncthreads();

    // ---- stage 2: block-level GEMM vs W, warp w = class w -------------------
    const int lane = tid & 31, cl = tid >> 5;   // cl in 0..9
    const float4* W4 = (const float4*)W;

    {
        float acc[NBPB];
#pragma unroll
        for (int b = 0; b < NBPB; ++b) acc[b] = 0.f;

        const float4* Wc = W4 + (size_t)cl * (NFEAT / 4) + chunk * 256;
#pragma unroll
        for (int j = 0; j < 8; ++j) {
            const int t = lane + 32 * j;
            const float4 w = __ldg(&Wc[t]);       // coalesced 512B/warp
#pragma unroll
            for (int b = 0; b < NBPB; ++b) {
                const float4 f = res_sm[b][t];    // conflict-free float4 LDS
                acc[b] += f.x * w.x + f.y * w.y + f.z * w.z + f.w * w.w;
            }
        }
#pragma unroll
        for (int b = 0; b < NBPB; ++b) {
#pragma unroll
            for (int off = 16; off; off >>= 1)
                acc[b] += __shfl_down_sync(0xffffffffu, acc[b], off);
        }
        if (lane == 0) {
#pragma unroll
            for (int b = 0; b < NBPB; ++b) {
                const int batch = blockIdx.x * NBPB + b;
                g_part[(batch * CHUNKS + chunk) * NC + cl] = acc[b];
            }
        }
    }
}

// ---------------- finalize: sum chunk partials, +bias, log_softmax ------------
// One block per batch, 10 warps = 10 classes. Lane l sums chunks l and l+32
// (parallel loads, ~2 load latencies instead of ~49), fixed shuffle tree.

__global__ __launch_bounds__(320)
void finalize_kernel(const float* __restrict__ bias,
                     float* __restrict__ out) {
    __shared__ float sl[NC];
    const int b = blockIdx.x;
    const int w = threadIdx.x >> 5;        // class
    const int lane = threadIdx.x & 31;

    float v = 0.f;
    {
        const float* gp = g_part + (size_t)b * CHUNKS * NC + w;
        if (lane < CHUNKS)      v  = gp[(size_t)lane * NC];
        if (lane + 32 < CHUNKS) v += gp[(size_t)(lane + 32) * NC];
    }
#pragma unroll
    for (int off = 16; off; off >>= 1)
        v += __shfl_down_sync(0xffffffffu, v, off);
    if (lane == 0) sl[w] = v + bias[w];
    __syncthreads();

    if (threadIdx.x < NC) {
        float mx = sl[0];
#pragma unroll
        for (int i = 1; i < NC; ++i) mx = fmaxf(mx, sl[i]);
        float se = 0.f;
#pragma unroll
        for (int i = 0; i < NC; ++i) se += expf(sl[i] - mx);
        out[b * NC + threadIdx.x] = sl[threadIdx.x] - mx - logf(se);
    }
}

extern "C" void kernel_launch(void* const* d_in, const int* in_sizes, int n_in,
                              void* d_out, int out_size) {
    const float* x    = (const float*)d_in[0];
    const float* rl1  = (const float*)d_in[1];
    const float* rl2  = (const float*)d_in[2];
    const float* W    = (const float*)d_in[3];
    const float* bias = (const float*)d_in[4];

    dim3 grid(NB / NBPB, CHUNKS);       // batch-group fastest for W L2 reuse
    quanv_kernel<<<grid, NTHR>>>(x, rl1, rl2, W);
    finalize_kernel<<<NB, 320>>>(bias, (float*)d_out);
}

// round 15
// speedup vs baseline: 1.0025x; 1.0025x over previous
#include <cuda_runtime.h>

#define IMG    224
#define PSIDE  112
#define NPATCH 12544          // PSIDE*PSIDE
#define CHUNKS 49             // NPATCH / 256
#define NFEAT  (4 * NPATCH)
#define NC     10
#define NB     32
#define NBPB   4              // batches per block (W reuse factor)
#define NTHR   320            // 10 warps: stage1 uses 8, stage2 one warp/class
#define NCOL   (NB / NBPB)    // 8 batch-group columns

// per-block partial class sums: [batch][chunk][class]
__device__ float g_part[NB * CHUNKS * NC];
// per-column arrival counters (zero-init at load; finalizer resets -> replay-safe)
__device__ int   g_count[NCOL];

// ---------------------------------------------------------------------------
// Closed-form quantum block (exact reduction of: encode_ry ; RY(p0)w0 ;
// RX(p1)w1 ; CNOT(0,1) ; RZ(p2)w2 ; RY(p3)w3 ; CNOT(2,3) ; RX(p4)w2 ;
// RZ(p5)w0 ; measure Z), verified in the Heisenberg picture:
//   z0 = cos(d0 + p0)                                   (CNOT control only)
//   z1 = cos(d0 + p0) * cos(p1) * cos(d1)               (Z⊗Z product form)
//   z2 = cos(p4)*cos(d2) + sin(p4)*sin(p2)*sin(d2)*sin(d3 + p3)
//   z3 = cos(d3 + p3) * cos(d2)
// (RZ(p5) is diagonal -> cannot change Z-basis probabilities -> dropped.)
//
// g layout (5 floats per layer): [0]=p0  [1]=cos(p1)  [2]=cos(p4)
//                                [3]=sin(p4)*sin(p2)  [4]=p3
// ---------------------------------------------------------------------------
__device__ __forceinline__ void qblock(const float d[4], const float* g, float out[4]) {
    float s2, c2, sB, cB;
    __sincosf(d[2],        &s2, &c2);
    __sincosf(d[3] + g[4], &sB, &cB);
    const float z0 = __cosf(d[0] + g[0]);
    out[0] = z0;
    out[1] = z0 * g[1] * __cosf(d[1]);
    out[2] = g[2] * c2 + g[3] * s2 * sB;
    out[3] = cB * c2;
}

// ---- fused kernel: patch extract + quantum blocks + block GEMM + finalize ----

__global__ __launch_bounds__(NTHR)
void quanv_kernel(const float* __restrict__ x,
                  const float* __restrict__ p1,
                  const float* __restrict__ p2,
                  const float* __restrict__ W,
                  const float* __restrict__ bias,
                  float* __restrict__ out) {
    __shared__ float  gc[10];              // 5 reduced constants per layer
    __shared__ float4 res_sm[NBPB][256];   // per-patch features, 16 KB
    __shared__ int    s_last;
    __shared__ float  sl[NBPB][NC];

    const int tid = threadIdx.x;
    if (tid >= 256 && tid < 256 + 10) {    // spare warps compute gate constants
        const int k = tid - 256;
        const int layer = k / 5, s = k % 5;
        const float* pp = (layer == 0) ? p1 : p2;
        float v;
        if      (s == 0) v = pp[0];
        else if (s == 1) v = cosf(pp[1]);
        else if (s == 2) v = cosf(pp[4]);
        else if (s == 3) v = sinf(pp[4]) * sinf(pp[2]);
        else             v = pp[3];
        gc[layer * 5 + s] = v;
    }
    __syncthreads();

    const int col   = blockIdx.x;          // batch-group column, 0..7
    const int chunk = blockIdx.y;          // 0..48

    // ---- stage 1: features for NBPB batches -> smem (first 8 warps) ---------
    if (tid < 256) {
        const int p  = chunk * 256 + tid;  // 0..12543
        const int pr = p / PSIDE, pc = p % PSIDE;
        const int r = 2 * pr, c = 2 * pc;
        const bool edge = (pc == PSIDE - 1);

#pragma unroll
        for (int b = 0; b < NBPB; ++b) {
            const int batch = col * NBPB + b;
            const float* xb = x + (size_t)batch * IMG * IMG + r * IMG + c;

            float d[4];
            float2 f01 = *(const float2*)xb;   // 8B aligned: c even
            d[0] = f01.x; d[1] = f01.y;
            if (edge) {                    // f2=x[r+1][c], f3=x[r+1][c+1]
                float2 f23 = *(const float2*)(xb + IMG);
                d[2] = f23.x; d[3] = f23.y;
            } else {                       // f2=x[r][c+2], f3=x[r+1][c]
                d[2] = xb[2];
                d[3] = xb[IMG];
            }

            float m[4], res[4];
            qblock(d, gc,     m);
            qblock(m, gc + 5, res);
            res_sm[b][tid] = make_float4(res[0] + m[0], res[1] + m[1],
                                         res[2] + m[2], res[3] + m[3]);
        }
    }
    __syncthreads();

    // ---- stage 2: block-level GEMM vs W, warp w = class w -------------------
    const int lane = tid & 31, cl = tid >> 5;   // cl in 0..9

    {
        float acc[NBPB];
#pragma unroll
        for (int b = 0; b < NBPB; ++b) acc[b] = 0.f;

        const float4* Wc = (const float4*)W + (size_t)cl * (NFEAT / 4) + chunk * 256;
#pragma unroll
        for (int j = 0; j < 8; ++j) {
            const int t = lane + 32 * j;
            const float4 w = __ldg(&Wc[t]);       // coalesced 512B/warp
#pragma unroll
            for (int b = 0; b < NBPB; ++b) {
                const float4 f = res_sm[b][t];    // conflict-free float4 LDS
                acc[b] += f.x * w.x + f.y * w.y + f.z * w.z + f.w * w.w;
            }
        }
#pragma unroll
        for (int b = 0; b < NBPB; ++b) {
#pragma unroll
            for (int off = 16; off; off >>= 1)
                acc[b] += __shfl_down_sync(0xffffffffu, acc[b], off);
        }
        if (lane == 0) {
#pragma unroll
            for (int b = 0; b < NBPB; ++b) {
                const int batch = col * NBPB + b;
                g_part[(batch * CHUNKS + chunk) * NC + cl] = acc[b];
            }
        }
    }

    // ---- stage 3: last block of this column finalizes its 4 batches ---------
    __syncthreads();
    if (tid == 0) {
        __threadfence();                        // publish g_part writes
        const int old = atomicAdd(&g_count[col], 1);
        s_last = (old == CHUNKS - 1);
    }
    __syncthreads();
    if (!s_last) return;

    __threadfence();                            // acquire other blocks' g_part

    // 40 threads: (local batch, class); fixed-order 49-chunk sum -> deterministic
    if (tid < NBPB * NC) {
        const int b  = tid / NC, c2 = tid % NC;
        const int batch = col * NBPB + b;
        const float* gp = g_part + (size_t)batch * CHUNKS * NC + c2;
        float v = 0.f;
#pragma unroll
        for (int ch = 0; ch < CHUNKS; ++ch)     // independent loads, high MLP
            v += gp[(size_t)ch * NC];
        sl[b][c2] = v + bias[c2];
    }
    __syncthreads();
    if (tid < NBPB * NC) {
        const int b  = tid / NC, c2 = tid % NC;
        const int batch = col * NBPB + b;
        float mx = sl[b][0];
#pragma unroll
        for (int i = 1; i < NC; ++i) mx = fmaxf(mx, sl[b][i]);
        float se = 0.f;
#pragma unroll
        for (int i = 0; i < NC; ++i) se += expf(sl[b][i] - mx);
        out[batch * NC + c2] = sl[b][c2] - mx - logf(se);
    }
    if (tid == 0) g_count[col] = 0;             // reset for next graph replay
}

extern "C" void kernel_launch(void* const* d_in, const int* in_sizes, int n_in,
                              void* d_out, int out_size) {
    const float* x    = (const float*)d_in[0];
    const float* rl1  = (const float*)d_in[1];
    const float* rl2  = (const float*)d_in[2];
    const float* W    = (const float*)d_in[3];
    const float* bias = (const float*)d_in[4];

    dim3 grid(NCOL, CHUNKS);            // batch-group fastest for W L2 reuse
    quanv_kernel<<<grid, NTHR>>>(x, rl1, rl2, W, bias, (float*)d_out);
}